// round 7
// baseline (speedup 1.0000x reference)
#include <cuda_runtime.h>
#include <cstdint>

// Residual quantizer, fp32, arithmetic mirror of the reference
// (validated rel_err 7.351969e-4, all FMA chains bitwise-preserved).
// Round 7: residual in REGISTERS (1 point/thread, 64 regs), codebook via
// warp-uniform smem broadcasts. Shared memory holds only the transposed
// codebook level (66.5 KB) -> 2 blocks/SM = 16 warps (4/SMSP), doubling
// latency-hiding vs rounds 4/6 (which were pinned at 8 warps by a 199 KB
// footprint). Per j per 16-code tile: 1 DUP + 4 uniform LDS + 8 FMA2.

#define KCODES 256
#define DIM 64
#define LEVELS 4
#define TPB 256
#define CST 260                  // C row stride (floats), 1040 B rows
#define C_BYTES (DIM * CST * 4)              // 66560
#define SMEM_BYTES (C_BYTES + KCODES * 4)    // 67584

#define FMA2(d, a, b, c) \
    asm("fma.rn.f32x2 %0, %1, %2, %3;" : "=l"(d) : "l"(a), "l"(b), "l"(c))
#define DUP2(d, s) asm("mov.b64 %0, {%1, %1};" : "=l"(d) : "f"(s))
#define LDS_V2U64(a, b, addr) \
    asm("ld.shared.v2.u64 {%0,%1}, [%2];" : "=l"(a), "=l"(b) : "r"(addr))

__global__ void __launch_bounds__(TPB, 2)
rq_kernel(const float* __restrict__ z, const float* __restrict__ cb,
          float* __restrict__ out, int B) {
    extern __shared__ __align__(16) char sm_raw[];
    float* C  = reinterpret_cast<float*>(sm_raw);
    float* c2 = reinterpret_cast<float*>(sm_raw + C_BYTES);

    const int tid = threadIdx.x;
    const long p_raw = (long)blockIdx.x * TPB + tid;
    const long p = p_raw < B ? p_raw : (B - 1);

    // ---- residual in registers ----
    float r[DIM];
    {
        const float4* zp = reinterpret_cast<const float4*>(z + p * DIM);
#pragma unroll
        for (int i = 0; i < 16; i++) {
            float4 v = zp[i];
            r[4 * i + 0] = v.x; r[4 * i + 1] = v.y;
            r[4 * i + 2] = v.z; r[4 * i + 3] = v.w;
        }
    }

    const unsigned smC = (unsigned)__cvta_generic_to_shared(C);
    int ids[LEVELS];

#pragma unroll 1
    for (int lvl = 0; lvl < LEVELS; lvl++) {
        __syncthreads();   // prev level's residual update read C
        // ---- stage codebook level transposed: C[j][tid] = cb[lvl][tid][j]
        {
            const float4* src = reinterpret_cast<const float4*>(
                cb + ((size_t)lvl * KCODES + tid) * DIM);
#pragma unroll
            for (int i = 0; i < 16; i++) {
                float4 v = src[i];
                C[(4 * i + 0) * CST + tid] = v.x;
                C[(4 * i + 1) * CST + tid] = v.y;
                C[(4 * i + 2) * CST + tid] = v.z;
                C[(4 * i + 3) * CST + tid] = v.w;
            }
        }
        __syncthreads();
        // ---- c2[k]: square-then-add, sequential over dims ----
        {
            float s = 0.f;
#pragma unroll
            for (int j = 0; j < DIM; j++) {
                float c = C[j * CST + tid];
                s = __fadd_rn(s, __fmul_rn(c, c));
            }
            c2[tid] = s;
        }
        __syncthreads();

        // ---- r2: sequential square-then-add ----
        float r2 = 0.f;
#pragma unroll
        for (int j = 0; j < DIM; j++)
            r2 = __fadd_rn(r2, __fmul_rn(r[j], r[j]));

        float best = __int_as_float(0x7F800000);
        int bi = 0;

        // ---- distance pass: 16 tiles x 16 codes, uniform code broadcasts
#pragma unroll 1
        for (int kt = 0; kt < 16; kt++) {
            const unsigned cA = smC + kt * 64;   // 16 codes * 4 B
            unsigned long long a[8];
#pragma unroll
            for (int m = 0; m < 8; m++) a[m] = 0ULL;

#pragma unroll 4
            for (int j = 0; j < DIM; j++) {
                unsigned long long rb;
                DUP2(rb, r[j]);
                unsigned long long c[8];
                const unsigned ca = cA + j * (CST * 4);
                LDS_V2U64(c[0], c[1], ca);
                LDS_V2U64(c[2], c[3], ca + 16);
                LDS_V2U64(c[4], c[5], ca + 32);
                LDS_V2U64(c[6], c[7], ca + 48);
#pragma unroll
                for (int m = 0; m < 8; m++) FMA2(a[m], rb, c[m], a[m]);
            }
            // ---- distances + argmin (ascending k, strict < => first-min)
#pragma unroll
            for (int m = 0; m < 8; m++) {
                const int k0 = kt * 16 + 2 * m;
                float lo, hi;
                asm("mov.b64 {%0,%1}, %2;" : "=f"(lo), "=f"(hi) : "l"(a[m]));
                float d0 = __fadd_rn(__fsub_rn(r2, __fmul_rn(2.0f, lo)),
                                     c2[k0]);
                float d1 = __fadd_rn(__fsub_rn(r2, __fmul_rn(2.0f, hi)),
                                     c2[k0 + 1]);
                if (d0 < best) { best = d0; bi = k0; }
                if (d1 < best) { best = d1; bi = k0 + 1; }
            }
        }
        ids[lvl] = bi;

        // ---- residual -= chosen code (per-lane gather from smem C) ----
#pragma unroll
        for (int j = 0; j < DIM; j++)
            r[j] = __fsub_rn(r[j], C[j * CST + bi]);
    }

    if (p_raw >= B) return;

    // ---- epilogue (chunk-wise; validated bitwise vs reference) ----
    {
        const float4* cp0 = reinterpret_cast<const float4*>(
            cb + ((size_t)0 * KCODES + ids[0]) * DIM);
        const float4* cp1 = reinterpret_cast<const float4*>(
            cb + ((size_t)1 * KCODES + ids[1]) * DIM);
        const float4* cp2 = reinterpret_cast<const float4*>(
            cb + ((size_t)2 * KCODES + ids[2]) * DIM);
        const float4* cp3 = reinterpret_cast<const float4*>(
            cb + ((size_t)3 * KCODES + ids[3]) * DIM);
        const float4* zp = reinterpret_cast<const float4*>(z + p * DIM);
        float4* qst = reinterpret_cast<float4*>(out + (size_t)p * DIM);
        float4* qq  = reinterpret_cast<float4*>(out + (size_t)B * (DIM + 4) +
                                                (size_t)p * DIM);
#pragma unroll
        for (int i = 0; i < 16; i++) {
            float4 v0 = __ldg(cp0 + i), v1 = __ldg(cp1 + i);
            float4 v2 = __ldg(cp2 + i), v3 = __ldg(cp3 + i);
            // quantized = ((q0 + q1) + q2) + q3, sequential (matches ref)
            float4 qv;
            qv.x = __fadd_rn(__fadd_rn(__fadd_rn(v0.x, v1.x), v2.x), v3.x);
            qv.y = __fadd_rn(__fadd_rn(__fadd_rn(v0.y, v1.y), v2.y), v3.y);
            qv.z = __fadd_rn(__fadd_rn(__fadd_rn(v0.z, v1.z), v2.z), v3.z);
            qv.w = __fadd_rn(__fadd_rn(__fadd_rn(v0.w, v1.w), v2.w), v3.w);
            float4 zv = zp[i];
            float4 sv;
            sv.x = __fadd_rn(zv.x, __fsub_rn(qv.x, zv.x));
            sv.y = __fadd_rn(zv.y, __fsub_rn(qv.y, zv.y));
            sv.z = __fadd_rn(zv.z, __fsub_rn(qv.z, zv.z));
            sv.w = __fadd_rn(zv.w, __fsub_rn(qv.w, zv.w));
            qst[i] = sv;
            qq[i] = qv;
        }
        float4 iv;
        iv.x = (float)ids[0]; iv.y = (float)ids[1];
        iv.z = (float)ids[2]; iv.w = (float)ids[3];
        reinterpret_cast<float4*>(out + (size_t)B * DIM)[p] = iv;
    }
}

extern "C" void kernel_launch(void* const* d_in, const int* in_sizes, int n_in,
                              void* d_out, int out_size) {
    const float* z = (const float*)d_in[0];
    const float* cb = (const float*)d_in[1];
    float* out = (float*)d_out;
    int B = in_sizes[0] / DIM;

    cudaFuncSetAttribute(rq_kernel, cudaFuncAttributeMaxDynamicSharedMemorySize,
                         SMEM_BYTES);
    int blocks = (B + TPB - 1) / TPB;
    rq_kernel<<<blocks, TPB, SMEM_BYTES>>>(z, cb, out, B);
}

// round 8
// speedup vs baseline: 1.4930x; 1.4930x over previous
#include <cuda_runtime.h>
#include <cstdint>

// Residual quantizer, fp32, arithmetic mirror of the reference
// (validated rel_err 7.351969e-4, all FMA chains bitwise-preserved).
// Round 8 = round 6 engine (best, 3173us: residual in smem per-lane,
// 2 pts/thread, 32-code tiles, warp-uniform code broadcasts) with a
// squeezed footprint for more warps:
//  * CST 260 -> 256 (broadcast loads don't need conflict padding): C 64 KB
//  * TPB 320 (640 pts/block): R 160 KB, total 230.4 KB -> 10 warps/SM (+25%)
//  * launch_bounds(320,1): reg cap ~200 (round 6 static demand ~150).
// fma-pipe roofline measured at ~1.83 ms; this round targets issue-eff.

#define KCODES 256
#define DIM 64
#define LEVELS 4
#define TPB 320
#define NPTS (TPB * 2)           // 640 points per block
#define RST NPTS                 // R row stride (floats) = 640
#define CST 256                  // C row stride (floats), 1024 B rows
#define R_BYTES (DIM * RST * 4)              // 163840
#define C_BYTES (DIM * CST * 4)              // 65536
#define SMEM_BYTES (R_BYTES + C_BYTES + KCODES * 4)   // 230400

#define FMA2(d, a, b, c) \
    asm("fma.rn.f32x2 %0, %1, %2, %3;" : "=l"(d) : "l"(a), "l"(b), "l"(c))
#define DUP2(d, s) asm("mov.b64 %0, {%1, %1};" : "=l"(d) : "f"(s))
#define LDS_V2U64(a, b, addr) \
    asm("ld.shared.v2.u64 {%0,%1}, [%2];" : "=l"(a), "=l"(b) : "r"(addr))

__global__ void __launch_bounds__(TPB, 1)
rq_kernel(const float* __restrict__ z, const float* __restrict__ cb,
          float* __restrict__ out, int B) {
    extern __shared__ __align__(16) char sm_raw[];
    float* R  = reinterpret_cast<float*>(sm_raw);
    float* C  = reinterpret_cast<float*>(sm_raw + R_BYTES);
    float* c2 = reinterpret_cast<float*>(sm_raw + R_BYTES + C_BYTES);

    const int tid = threadIdx.x;
    const int lp0 = 2 * tid;
    const long p0_raw = (long)blockIdx.x * NPTS + lp0;
    const long p0 = p0_raw < B ? p0_raw : (B - 1);
    const long p1 = (p0_raw + 1) < B ? (p0_raw + 1) : (B - 1);

    // ---- init residual R[j][lp0..lp0+1] = z ----
    {
        const float4* z0 = reinterpret_cast<const float4*>(z + p0 * DIM);
        const float4* z1 = reinterpret_cast<const float4*>(z + p1 * DIM);
#pragma unroll
        for (int i = 0; i < 16; i++) {
            float4 a = z0[i], b = z1[i];
            *reinterpret_cast<float2*>(R + (4 * i + 0) * RST + lp0) =
                make_float2(a.x, b.x);
            *reinterpret_cast<float2*>(R + (4 * i + 1) * RST + lp0) =
                make_float2(a.y, b.y);
            *reinterpret_cast<float2*>(R + (4 * i + 2) * RST + lp0) =
                make_float2(a.z, b.z);
            *reinterpret_cast<float2*>(R + (4 * i + 3) * RST + lp0) =
                make_float2(a.w, b.w);
        }
    }

    const unsigned smR = (unsigned)__cvta_generic_to_shared(R) + lp0 * 4;
    const unsigned smC = (unsigned)__cvta_generic_to_shared(C);

    int id0[LEVELS], id1[LEVELS];

#pragma unroll 1
    for (int lvl = 0; lvl < LEVELS; lvl++) {
        __syncthreads();   // prev level's residual update read C
        // ---- stage codebook level transposed: C[j][k] = cb[lvl][k][j] ----
        if (tid < KCODES) {
            const float4* src = reinterpret_cast<const float4*>(
                cb + ((size_t)lvl * KCODES + tid) * DIM);
#pragma unroll
            for (int i = 0; i < 16; i++) {
                float4 v = src[i];
                C[(4 * i + 0) * CST + tid] = v.x;
                C[(4 * i + 1) * CST + tid] = v.y;
                C[(4 * i + 2) * CST + tid] = v.z;
                C[(4 * i + 3) * CST + tid] = v.w;
            }
        }
        __syncthreads();
        // ---- c2[k]: square-then-add, sequential over dims ----
        if (tid < KCODES) {
            float s = 0.f;
#pragma unroll
            for (int j = 0; j < DIM; j++) {
                float c = C[j * CST + tid];
                s = __fadd_rn(s, __fmul_rn(c, c));
            }
            c2[tid] = s;
        }
        __syncthreads();

        // ---- r2 for my 2 points (sequential chains) ----
        float r2a = 0.f, r2b = 0.f;
#pragma unroll
        for (int j = 0; j < DIM; j++) {
            float2 rv = *reinterpret_cast<const float2*>(R + j * RST + lp0);
            r2a = __fadd_rn(r2a, __fmul_rn(rv.x, rv.x));
            r2b = __fadd_rn(r2b, __fmul_rn(rv.y, rv.y));
        }

        float best0 = __int_as_float(0x7F800000);
        float best1 = __int_as_float(0x7F800000);
        int bi0 = 0, bi1 = 0;

        // ---- distance pass: 8 tiles of 32 codes, warp-uniform code loads
#pragma unroll 1
        for (int kt = 0; kt < 8; kt++) {
            const unsigned cA = smC + kt * 128;   // 32 codes * 4 B
            unsigned long long a0[16], a1[16];
#pragma unroll
            for (int m = 0; m < 16; m++) { a0[m] = 0ULL; a1[m] = 0ULL; }

#pragma unroll 8
            for (int j = 0; j < DIM; j++) {
                float rx, ry;
                asm("ld.shared.v2.f32 {%0,%1}, [%2];"
                    : "=f"(rx), "=f"(ry) : "r"(smR + j * (RST * 4)));
                unsigned long long ra, rb;
                DUP2(ra, rx); DUP2(rb, ry);
                unsigned long long c[16];
                const unsigned ca = cA + j * (CST * 4);
                LDS_V2U64(c[0],  c[1],  ca);
                LDS_V2U64(c[2],  c[3],  ca + 16);
                LDS_V2U64(c[4],  c[5],  ca + 32);
                LDS_V2U64(c[6],  c[7],  ca + 48);
                LDS_V2U64(c[8],  c[9],  ca + 64);
                LDS_V2U64(c[10], c[11], ca + 80);
                LDS_V2U64(c[12], c[13], ca + 96);
                LDS_V2U64(c[14], c[15], ca + 112);
#pragma unroll
                for (int m = 0; m < 16; m++) FMA2(a0[m], ra, c[m], a0[m]);
#pragma unroll
                for (int m = 0; m < 16; m++) FMA2(a1[m], rb, c[m], a1[m]);
            }
            // ---- distances + argmin (ascending k, strict < => first-min)
#pragma unroll
            for (int m = 0; m < 16; m++) {
                const int k0 = kt * 32 + 2 * m;
                const float cc0 = c2[k0], cc1 = c2[k0 + 1];
                float lo, hi;
                asm("mov.b64 {%0,%1}, %2;" : "=f"(lo), "=f"(hi) : "l"(a0[m]));
                float d0 = __fadd_rn(__fsub_rn(r2a, __fmul_rn(2.0f, lo)), cc0);
                float d1 = __fadd_rn(__fsub_rn(r2a, __fmul_rn(2.0f, hi)), cc1);
                if (d0 < best0) { best0 = d0; bi0 = k0; }
                if (d1 < best0) { best0 = d1; bi0 = k0 + 1; }
                asm("mov.b64 {%0,%1}, %2;" : "=f"(lo), "=f"(hi) : "l"(a1[m]));
                float e0 = __fadd_rn(__fsub_rn(r2b, __fmul_rn(2.0f, lo)), cc0);
                float e1 = __fadd_rn(__fsub_rn(r2b, __fmul_rn(2.0f, hi)), cc1);
                if (e0 < best1) { best1 = e0; bi1 = k0; }
                if (e1 < best1) { best1 = e1; bi1 = k0 + 1; }
            }
        }
        id0[lvl] = bi0; id1[lvl] = bi1;

        // ---- residual update (reads C; next sync at loop top) ----
#pragma unroll
        for (int j = 0; j < DIM; j++) {
            float2 rv = *reinterpret_cast<const float2*>(R + j * RST + lp0);
            rv.x = __fsub_rn(rv.x, C[j * CST + bi0]);
            rv.y = __fsub_rn(rv.y, C[j * CST + bi1]);
            *reinterpret_cast<float2*>(R + j * RST + lp0) = rv;
        }
    }

    // ---- epilogue (chunk-wise, low reg pressure) ----
    const long pts[2] = {p0, p1};
    const bool valid[2] = {p0_raw < B, (p0_raw + 1) < B};
#pragma unroll 1
    for (int s = 0; s < 2; s++) {
        if (!valid[s]) continue;
        const long p = pts[s];
        const int* ids = (s == 0) ? id0 : id1;
        const float4* cp0 = reinterpret_cast<const float4*>(
            cb + ((size_t)0 * KCODES + ids[0]) * DIM);
        const float4* cp1 = reinterpret_cast<const float4*>(
            cb + ((size_t)1 * KCODES + ids[1]) * DIM);
        const float4* cp2 = reinterpret_cast<const float4*>(
            cb + ((size_t)2 * KCODES + ids[2]) * DIM);
        const float4* cp3 = reinterpret_cast<const float4*>(
            cb + ((size_t)3 * KCODES + ids[3]) * DIM);
        const float4* zp = reinterpret_cast<const float4*>(z + p * DIM);
        float4* qst = reinterpret_cast<float4*>(out + (size_t)p * DIM);
        float4* qq  = reinterpret_cast<float4*>(out + (size_t)B * (DIM + 4) +
                                                (size_t)p * DIM);
#pragma unroll
        for (int i = 0; i < 16; i++) {
            float4 v0 = __ldg(cp0 + i), v1 = __ldg(cp1 + i);
            float4 v2 = __ldg(cp2 + i), v3 = __ldg(cp3 + i);
            // quantized = ((q0 + q1) + q2) + q3, sequential (matches ref)
            float4 qv;
            qv.x = __fadd_rn(__fadd_rn(__fadd_rn(v0.x, v1.x), v2.x), v3.x);
            qv.y = __fadd_rn(__fadd_rn(__fadd_rn(v0.y, v1.y), v2.y), v3.y);
            qv.z = __fadd_rn(__fadd_rn(__fadd_rn(v0.z, v1.z), v2.z), v3.z);
            qv.w = __fadd_rn(__fadd_rn(__fadd_rn(v0.w, v1.w), v2.w), v3.w);
            float4 zv = zp[i];
            float4 sv;
            sv.x = __fadd_rn(zv.x, __fsub_rn(qv.x, zv.x));
            sv.y = __fadd_rn(zv.y, __fsub_rn(qv.y, zv.y));
            sv.z = __fadd_rn(zv.z, __fsub_rn(qv.z, zv.z));
            sv.w = __fadd_rn(zv.w, __fsub_rn(qv.w, zv.w));
            qst[i] = sv;
            qq[i] = qv;
        }
        float4 iv;
        iv.x = (float)ids[0]; iv.y = (float)ids[1];
        iv.z = (float)ids[2]; iv.w = (float)ids[3];
        reinterpret_cast<float4*>(out + (size_t)B * DIM)[p] = iv;
    }
}

extern "C" void kernel_launch(void* const* d_in, const int* in_sizes, int n_in,
                              void* d_out, int out_size) {
    const float* z = (const float*)d_in[0];
    const float* cb = (const float*)d_in[1];
    float* out = (float*)d_out;
    int B = in_sizes[0] / DIM;

    cudaFuncSetAttribute(rq_kernel, cudaFuncAttributeMaxDynamicSharedMemorySize,
                         SMEM_BYTES);
    int blocks = (B + NPTS - 1) / NPTS;
    rq_kernel<<<blocks, TPB, SMEM_BYTES>>>(z, cb, out, B);
}